// round 2
// baseline (speedup 1.0000x reference)
#include <cuda_runtime.h>

// ---------------------------------------------------------------------------
// StructureAwareAttention on GB300
//   N=50000 nodes, C=128, E=800000 edges, HEADS=4, HEAD_DIM=32
// Plan:
//   K0 zero counts
//   K1 QKV gemm (x[N,128] @ {Wq,Wk,Wv}[128,128] + b)   -> g_q/g_k/g_v
//   K2 histogram of dst
//   K3 single-block exclusive scan -> CSR offsets + cursor
//   K4 scatter edges into CSR order (packed src|stype)
//   K5 per-node warp gather: scores + softmax (max-free) + weighted-V, no atomics
//   K6 output gemm + bias + residual + LayerNorm (fused epilogue)
// ---------------------------------------------------------------------------

#define NMAX 50000
#define EMAX 800000

__device__ float g_q[(size_t)NMAX * 128];
__device__ float g_k[(size_t)NMAX * 128];
__device__ float g_v[(size_t)NMAX * 128];
__device__ float g_att[(size_t)NMAX * 128];
__device__ int   g_cnt[NMAX];
__device__ int   g_off[NMAX + 1];
__device__ int   g_cur[NMAX];
__device__ int   g_packed[EMAX];

// ---------------------------------------------------------------- K0: zero
__global__ void zero_cnt_kernel(int n) {
    int i = blockIdx.x * blockDim.x + threadIdx.x;
    if (i < n) g_cnt[i] = 0;
}

// ---------------------------------------------------------------- K1: QKV GEMM
// blockIdx.y selects {q,k,v}. Block: 256 threads, tile 64 rows x 128 cols, K=128
// (K chunked by 32 so static smem = 32KB + 16KB = 48KB).
__global__ __launch_bounds__(256) void qkv_gemm_kernel(
    const float* __restrict__ x,
    const float* __restrict__ Wq, const float* __restrict__ bq,
    const float* __restrict__ Wk, const float* __restrict__ bk,
    const float* __restrict__ Wv, const float* __restrict__ bv,
    int n)
{
    __shared__ __align__(16) float sX[64][128];
    __shared__ __align__(16) float sW[32][128];

    const float* W; const float* bias; float* out;
    if (blockIdx.y == 0)      { W = Wq; bias = bq; out = g_q; }
    else if (blockIdx.y == 1) { W = Wk; bias = bk; out = g_k; }
    else                      { W = Wv; bias = bv; out = g_v; }

    int tid  = threadIdx.x;
    int row0 = blockIdx.x * 64;

    // load X tile (float4, coalesced)
    for (int i = tid; i < 64 * 32; i += 256) {
        int r = i >> 5, c = i & 31;
        float4 val = make_float4(0.f, 0.f, 0.f, 0.f);
        if (row0 + r < n)
            val = ((const float4*)x)[(size_t)(row0 + r) * 32 + c];
        *((float4*)&sX[r][0] + c) = val;
    }

    int warp = tid >> 5, lane = tid & 31;
    int r0 = warp * 8;

    float acc[8][4];
#pragma unroll
    for (int i = 0; i < 8; i++) { acc[i][0] = acc[i][1] = acc[i][2] = acc[i][3] = 0.f; }

    for (int kc = 0; kc < 128; kc += 32) {
        __syncthreads();
        for (int i = tid; i < 32 * 32; i += 256) {
            int r = i >> 5, c = i & 31;
            *((float4*)&sW[r][0] + c) = ((const float4*)W)[(size_t)(kc + r) * 32 + c];
        }
        __syncthreads();
#pragma unroll
        for (int kk = 0; kk < 32; kk++) {
            float4 bv4 = *((const float4*)&sW[kk][0] + lane);
#pragma unroll
            for (int i2 = 0; i2 < 8; i2++) {
                float a = sX[r0 + i2][kc + kk];  // broadcast LDS
                acc[i2][0] += a * bv4.x;
                acc[i2][1] += a * bv4.y;
                acc[i2][2] += a * bv4.z;
                acc[i2][3] += a * bv4.w;
            }
        }
    }

    float4 b4 = *((const float4*)bias + lane);
#pragma unroll
    for (int i2 = 0; i2 < 8; i2++) {
        int r = row0 + r0 + i2;
        if (r < n) {
            float4 o;
            o.x = acc[i2][0] + b4.x;
            o.y = acc[i2][1] + b4.y;
            o.z = acc[i2][2] + b4.z;
            o.w = acc[i2][3] + b4.w;
            ((float4*)out)[(size_t)r * 32 + lane] = o;
        }
    }
}

// ---------------------------------------------------------------- K2: histogram
__global__ void hist_kernel(const int* __restrict__ dst, int e) {
    int i = blockIdx.x * blockDim.x + threadIdx.x;
    if (i < e) atomicAdd(&g_cnt[dst[i]], 1);
}

// ---------------------------------------------------------------- K3: scan (1 block)
__global__ __launch_bounds__(1024) void scan_kernel(int n) {
    __shared__ int s[1024];
    int tid = threadIdx.x;
    int running = 0;
    for (int base = 0; base < n; base += 1024) {
        int i = base + tid;
        int val = (i < n) ? g_cnt[i] : 0;
        s[tid] = val;
        __syncthreads();
        for (int d = 1; d < 1024; d <<= 1) {
            int t = (tid >= d) ? s[tid - d] : 0;
            __syncthreads();
            s[tid] += t;
            __syncthreads();
        }
        int excl = running + s[tid] - val;
        if (i < n) { g_off[i] = excl; g_cur[i] = excl; }
        running += s[1023];
        __syncthreads();
    }
    if (tid == 0) g_off[n] = running;
}

// ---------------------------------------------------------------- K4: scatter
__global__ void scatter_kernel(const int* __restrict__ src,
                               const int* __restrict__ dst,
                               const int* __restrict__ stype, int e) {
    int i = blockIdx.x * blockDim.x + threadIdx.x;
    if (i < e) {
        int d = dst[i];
        int p = atomicAdd(&g_cur[d], 1);
        int s_ = src[i];
        g_packed[p] = s_ | (stype[s_] << 20);
    }
}

// ---------------------------------------------------------------- K5: gather
// One warp per node. Lane l owns dims [4l,4l+4) => head = l>>3.
// Online max-free softmax: scores ~N(0,1), exp stays well in fp32 range; the
// e/sum ratio is mathematically identical to the (max-subtracted) reference.
__global__ __launch_bounds__(256) void gather_kernel(
    const float* __restrict__ sbias, int n)
{
    int node = (blockIdx.x * blockDim.x + threadIdx.x) >> 5;
    int lane = threadIdx.x & 31;
    if (node >= n) return;

    int head = lane >> 3;
    float b0 = sbias[0 * 4 + head];
    float b1 = sbias[1 * 4 + head];
    float b2 = sbias[2 * 4 + head];

    const float4* kp = (const float4*)g_k;
    const float4* vp = (const float4*)g_v;
    float4 q4 = ((const float4*)g_q)[(size_t)node * 32 + lane];

    float4 acc = make_float4(0.f, 0.f, 0.f, 0.f);
    float ssum = 0.f;
    const float INV_SQRT_HD = 0.17677669529663689f;  // 1/sqrt(32)

    int beg = g_off[node], end = g_off[node + 1];
    int j = beg;
    for (; j + 1 < end; j += 2) {
        int w0 = g_packed[j], w1 = g_packed[j + 1];
        int s0 = w0 & 0xFFFFF, t0 = w0 >> 20;
        int s1 = w1 & 0xFFFFF, t1 = w1 >> 20;
        float4 ka = kp[(size_t)s0 * 32 + lane];
        float4 kb = kp[(size_t)s1 * 32 + lane];
        float4 va = vp[(size_t)s0 * 32 + lane];
        float4 vb = vp[(size_t)s1 * 32 + lane];

        float pa = q4.x * ka.x + q4.y * ka.y + q4.z * ka.z + q4.w * ka.w;
        float pb = q4.x * kb.x + q4.y * kb.y + q4.z * kb.z + q4.w * kb.w;
        pa += __shfl_xor_sync(0xffffffffu, pa, 1);
        pb += __shfl_xor_sync(0xffffffffu, pb, 1);
        pa += __shfl_xor_sync(0xffffffffu, pa, 2);
        pb += __shfl_xor_sync(0xffffffffu, pb, 2);
        pa += __shfl_xor_sync(0xffffffffu, pa, 4);
        pb += __shfl_xor_sync(0xffffffffu, pb, 4);

        float ba = (t0 == 0) ? b0 : ((t0 == 1) ? b1 : b2);
        float bb = (t1 == 0) ? b0 : ((t1 == 1) ? b1 : b2);
        float ea = __expf(pa * INV_SQRT_HD + ba);
        float eb = __expf(pb * INV_SQRT_HD + bb);
        ssum += ea + eb;
        acc.x += ea * va.x + eb * vb.x;
        acc.y += ea * va.y + eb * vb.y;
        acc.z += ea * va.z + eb * vb.z;
        acc.w += ea * va.w + eb * vb.w;
    }
    if (j < end) {
        int w0 = g_packed[j];
        int s0 = w0 & 0xFFFFF, t0 = w0 >> 20;
        float4 ka = kp[(size_t)s0 * 32 + lane];
        float4 va = vp[(size_t)s0 * 32 + lane];
        float pa = q4.x * ka.x + q4.y * ka.y + q4.z * ka.z + q4.w * ka.w;
        pa += __shfl_xor_sync(0xffffffffu, pa, 1);
        pa += __shfl_xor_sync(0xffffffffu, pa, 2);
        pa += __shfl_xor_sync(0xffffffffu, pa, 4);
        float ba = (t0 == 0) ? b0 : ((t0 == 1) ? b1 : b2);
        float ea = __expf(pa * INV_SQRT_HD + ba);
        ssum += ea;
        acc.x += ea * va.x;
        acc.y += ea * va.y;
        acc.z += ea * va.z;
        acc.w += ea * va.w;
    }

    float inv = 1.f / (ssum + 1e-16f);
    float4 o;
    o.x = acc.x * inv; o.y = acc.y * inv; o.z = acc.z * inv; o.w = acc.w * inv;
    ((float4*)g_att)[(size_t)node * 32 + lane] = o;
}

// ---------------------------------------------------------------- K6: out gemm + LN
__global__ __launch_bounds__(256) void out_ln_kernel(
    const float* __restrict__ x,
    const float* __restrict__ Wo, const float* __restrict__ bo,
    const float* __restrict__ gamma, const float* __restrict__ beta,
    float* __restrict__ out, int n)
{
    __shared__ __align__(16) float sX[64][128];
    __shared__ __align__(16) float sW[32][128];

    int tid  = threadIdx.x;
    int row0 = blockIdx.x * 64;

    for (int i = tid; i < 64 * 32; i += 256) {
        int r = i >> 5, c = i & 31;
        float4 val = make_float4(0.f, 0.f, 0.f, 0.f);
        if (row0 + r < n)
            val = ((const float4*)g_att)[(size_t)(row0 + r) * 32 + c];
        *((float4*)&sX[r][0] + c) = val;
    }

    int warp = tid >> 5, lane = tid & 31;
    int r0 = warp * 8;

    float acc[8][4];
#pragma unroll
    for (int i = 0; i < 8; i++) { acc[i][0] = acc[i][1] = acc[i][2] = acc[i][3] = 0.f; }

    for (int kc = 0; kc < 128; kc += 32) {
        __syncthreads();
        for (int i = tid; i < 32 * 32; i += 256) {
            int r = i >> 5, c = i & 31;
            *((float4*)&sW[r][0] + c) = ((const float4*)Wo)[(size_t)(kc + r) * 32 + c];
        }
        __syncthreads();
#pragma unroll
        for (int kk = 0; kk < 32; kk++) {
            float4 bv4 = *((const float4*)&sW[kk][0] + lane);
#pragma unroll
            for (int i2 = 0; i2 < 8; i2++) {
                float a = sX[r0 + i2][kc + kk];
                acc[i2][0] += a * bv4.x;
                acc[i2][1] += a * bv4.y;
                acc[i2][2] += a * bv4.z;
                acc[i2][3] += a * bv4.w;
            }
        }
    }

    float4 b4 = *((const float4*)bo + lane);
    float4 g4 = *((const float4*)gamma + lane);
    float4 t4 = *((const float4*)beta + lane);

#pragma unroll
    for (int i2 = 0; i2 < 8; i2++) {
        int r = row0 + r0 + i2;
        if (r >= n) continue;  // uniform per warp
        float4 xr = ((const float4*)x)[(size_t)r * 32 + lane];
        float y0 = acc[i2][0] + b4.x + xr.x;
        float y1 = acc[i2][1] + b4.y + xr.y;
        float y2 = acc[i2][2] + b4.z + xr.z;
        float y3 = acc[i2][3] + b4.w + xr.w;

        float sum = y0 + y1 + y2 + y3;
        float sq  = y0 * y0 + y1 * y1 + y2 * y2 + y3 * y3;
#pragma unroll
        for (int m = 16; m; m >>= 1) {
            sum += __shfl_xor_sync(0xffffffffu, sum, m);
            sq  += __shfl_xor_sync(0xffffffffu, sq, m);
        }
        float mu   = sum * (1.f / 128.f);
        float var  = sq * (1.f / 128.f) - mu * mu;
        float rstd = rsqrtf(var + 1e-5f);

        float4 o;
        o.x = (y0 - mu) * rstd * g4.x + t4.x;
        o.y = (y1 - mu) * rstd * g4.y + t4.y;
        o.z = (y2 - mu) * rstd * g4.z + t4.z;
        o.w = (y3 - mu) * rstd * g4.w + t4.w;
        ((float4*)out)[(size_t)r * 32 + lane] = o;
    }
}

// ---------------------------------------------------------------- launch
extern "C" void kernel_launch(void* const* d_in, const int* in_sizes, int n_in,
                              void* d_out, int out_size)
{
    const float* x     = (const float*)d_in[0];
    const int*   stype = (const int*)d_in[1];
    const int*   eidx  = (const int*)d_in[2];
    const float* Wq    = (const float*)d_in[3];
    const float* bq    = (const float*)d_in[4];
    const float* Wk    = (const float*)d_in[5];
    const float* bk    = (const float*)d_in[6];
    const float* Wv    = (const float*)d_in[7];
    const float* bv    = (const float*)d_in[8];
    const float* sbias = (const float*)d_in[9];
    const float* Wo    = (const float*)d_in[10];
    const float* bo    = (const float*)d_in[11];
    const float* gam   = (const float*)d_in[12];
    const float* bet   = (const float*)d_in[13];

    int n = in_sizes[0] / 128;
    int e = in_sizes[2] / 2;
    const int* src = eidx;
    const int* dst = eidx + e;

    zero_cnt_kernel<<<(n + 255) / 256, 256>>>(n);
    qkv_gemm_kernel<<<dim3((n + 63) / 64, 3), 256>>>(x, Wq, bq, Wk, bk, Wv, bv, n);
    hist_kernel<<<(e + 255) / 256, 256>>>(dst, e);
    scan_kernel<<<1, 1024>>>(n);
    scatter_kernel<<<(e + 255) / 256, 256>>>(src, dst, stype, e);
    gather_kernel<<<((size_t)n * 32 + 255) / 256, 256>>>(sbias, n);
    out_ln_kernel<<<(n + 63) / 64, 256>>>(x, Wo, bo, gam, bet, (float*)d_out, n);
}

// round 3
// speedup vs baseline: 1.2151x; 1.2151x over previous
#include <cuda_runtime.h>

// ---------------------------------------------------------------------------
// StructureAwareAttention on GB300
//   N=50000 nodes, C=128, E=800000 edges, HEADS=4, HEAD_DIM=32
// Pipeline:
//   K0 zero counts
//   K1 QKV gemm (x[N,128] @ {Wq,Wk,Wv}[128,128] + b)   -> g_q/g_k/g_v
//   K2 histogram of dst
//   S1/S2/S3 multi-block work-efficient exclusive scan -> CSR offsets
//   K4 scatter edges into CSR order (packed src|stype)
//   K5 per-node warp gather: scores + softmax (max-free) + weighted-V
//   K6 output gemm + bias + residual + LayerNorm (fused epilogue)
// ---------------------------------------------------------------------------

#define NMAX 50000
#define EMAX 800000
#define SCAN_B 1024
#define NBLK ((NMAX + SCAN_B - 1) / SCAN_B)   // 49

__device__ float g_q[(size_t)NMAX * 128];
__device__ float g_k[(size_t)NMAX * 128];
__device__ float g_v[(size_t)NMAX * 128];
__device__ float g_att[(size_t)NMAX * 128];
__device__ int   g_cnt[NMAX];
__device__ int   g_off[NMAX + 1];
__device__ int   g_cur[NMAX];
__device__ int   g_packed[EMAX];
__device__ int   g_bsum[64];
__device__ int   g_boff[64];

// ---------------------------------------------------------------- K0: zero
__global__ void zero_cnt_kernel(int n) {
    int i = blockIdx.x * blockDim.x + threadIdx.x;
    if (i < n) g_cnt[i] = 0;
}

// ---------------------------------------------------------------- K1: QKV GEMM
__global__ __launch_bounds__(256) void qkv_gemm_kernel(
    const float* __restrict__ x,
    const float* __restrict__ Wq, const float* __restrict__ bq,
    const float* __restrict__ Wk, const float* __restrict__ bk,
    const float* __restrict__ Wv, const float* __restrict__ bv,
    int n)
{
    __shared__ __align__(16) float sX[64][128];
    __shared__ __align__(16) float sW[32][128];

    const float* W; const float* bias; float* out;
    if (blockIdx.y == 0)      { W = Wq; bias = bq; out = g_q; }
    else if (blockIdx.y == 1) { W = Wk; bias = bk; out = g_k; }
    else                      { W = Wv; bias = bv; out = g_v; }

    int tid  = threadIdx.x;
    int row0 = blockIdx.x * 64;

    for (int i = tid; i < 64 * 32; i += 256) {
        int r = i >> 5, c = i & 31;
        float4 val = make_float4(0.f, 0.f, 0.f, 0.f);
        if (row0 + r < n)
            val = ((const float4*)x)[(size_t)(row0 + r) * 32 + c];
        *((float4*)&sX[r][0] + c) = val;
    }

    int warp = tid >> 5, lane = tid & 31;
    int r0 = warp * 8;

    float acc[8][4];
#pragma unroll
    for (int i = 0; i < 8; i++) { acc[i][0] = acc[i][1] = acc[i][2] = acc[i][3] = 0.f; }

    for (int kc = 0; kc < 128; kc += 32) {
        __syncthreads();
        for (int i = tid; i < 32 * 32; i += 256) {
            int r = i >> 5, c = i & 31;
            *((float4*)&sW[r][0] + c) = ((const float4*)W)[(size_t)(kc + r) * 32 + c];
        }
        __syncthreads();
#pragma unroll
        for (int kk = 0; kk < 32; kk++) {
            float4 bv4 = *((const float4*)&sW[kk][0] + lane);
#pragma unroll
            for (int i2 = 0; i2 < 8; i2++) {
                float a = sX[r0 + i2][kc + kk];
                acc[i2][0] += a * bv4.x;
                acc[i2][1] += a * bv4.y;
                acc[i2][2] += a * bv4.z;
                acc[i2][3] += a * bv4.w;
            }
        }
    }

    float4 b4 = *((const float4*)bias + lane);
#pragma unroll
    for (int i2 = 0; i2 < 8; i2++) {
        int r = row0 + r0 + i2;
        if (r < n) {
            float4 o;
            o.x = acc[i2][0] + b4.x;
            o.y = acc[i2][1] + b4.y;
            o.z = acc[i2][2] + b4.z;
            o.w = acc[i2][3] + b4.w;
            ((float4*)out)[(size_t)r * 32 + lane] = o;
        }
    }
}

// ---------------------------------------------------------------- K2: histogram
__global__ void hist_kernel(const int* __restrict__ dst, int e) {
    int i = blockIdx.x * blockDim.x + threadIdx.x;
    if (i < e) atomicAdd(&g_cnt[dst[i]], 1);
}

// ---------------------------------------------------------------- S1: block scan
__global__ __launch_bounds__(SCAN_B) void scan1_kernel(int n) {
    __shared__ int wsum[32];
    int tid  = threadIdx.x;
    int lane = tid & 31, wid = tid >> 5;
    int i = blockIdx.x * SCAN_B + tid;
    int val = (i < n) ? g_cnt[i] : 0;

    // warp inclusive scan
    int x = val;
#pragma unroll
    for (int d = 1; d < 32; d <<= 1) {
        int t = __shfl_up_sync(0xffffffffu, x, d);
        if (lane >= d) x += t;
    }
    if (lane == 31) wsum[wid] = x;
    __syncthreads();
    if (wid == 0) {
        int w = wsum[lane];
#pragma unroll
        for (int d = 1; d < 32; d <<= 1) {
            int t = __shfl_up_sync(0xffffffffu, w, d);
            if (lane >= d) w += t;
        }
        wsum[lane] = w;
    }
    __syncthreads();
    int base = (wid > 0) ? wsum[wid - 1] : 0;
    int incl = x + base;
    if (i < n) g_off[i] = incl - val;        // local exclusive
    if (tid == SCAN_B - 1) g_bsum[blockIdx.x] = incl;
}

// ---------------------------------------------------------------- S2: scan blocks
__global__ void scan2_kernel(int nb, int n) {
    // nb <= 64: two-warp shuffle scan via smem
    __shared__ int s[64];
    int tid = threadIdx.x;
    int val = (tid < nb) ? g_bsum[tid] : 0;
    s[tid] = val;
    __syncthreads();
#pragma unroll
    for (int d = 1; d < 64; d <<= 1) {
        int t = (tid >= d) ? s[tid - d] : 0;
        __syncthreads();
        s[tid] += t;
        __syncthreads();
    }
    if (tid < nb) g_boff[tid] = s[tid] - val;  // exclusive
    if (tid == 63) g_off[n] = s[63];           // total
}

// ---------------------------------------------------------------- S3: add base
__global__ __launch_bounds__(SCAN_B) void scan3_kernel(int n) {
    int i = blockIdx.x * SCAN_B + threadIdx.x;
    if (i < n) {
        int v = g_off[i] + g_boff[blockIdx.x];
        g_off[i] = v;
        g_cur[i] = v;
    }
}

// ---------------------------------------------------------------- K4: scatter
__global__ void scatter_kernel(const int* __restrict__ src,
                               const int* __restrict__ dst,
                               const int* __restrict__ stype, int e) {
    int i = blockIdx.x * blockDim.x + threadIdx.x;
    if (i < e) {
        int d = dst[i];
        int p = atomicAdd(&g_cur[d], 1);
        int s_ = src[i];
        g_packed[p] = s_ | (stype[s_] << 20);
    }
}

// ---------------------------------------------------------------- K5: gather
// One warp per node. Lane l owns dims [4l,4l+4) => head = l>>3.
// Max-free softmax: scores ~N(0,1); exp stays well within fp32 range and the
// e/sum ratio is mathematically identical to the max-subtracted reference.
__global__ __launch_bounds__(256) void gather_kernel(
    const float* __restrict__ sbias, int n)
{
    int node = (blockIdx.x * blockDim.x + threadIdx.x) >> 5;
    int lane = threadIdx.x & 31;
    if (node >= n) return;

    int head = lane >> 3;
    float b0 = sbias[0 * 4 + head];
    float b1 = sbias[1 * 4 + head];
    float b2 = sbias[2 * 4 + head];

    const float4* kp = (const float4*)g_k;
    const float4* vp = (const float4*)g_v;
    float4 q4 = ((const float4*)g_q)[(size_t)node * 32 + lane];

    float4 acc = make_float4(0.f, 0.f, 0.f, 0.f);
    float ssum = 0.f;
    const float INV_SQRT_HD = 0.17677669529663689f;  // 1/sqrt(32)

    int beg = g_off[node], end = g_off[node + 1];
    int j = beg;
    for (; j + 1 < end; j += 2) {
        int w0 = g_packed[j], w1 = g_packed[j + 1];
        int s0 = w0 & 0xFFFFF, t0 = w0 >> 20;
        int s1 = w1 & 0xFFFFF, t1 = w1 >> 20;
        float4 ka = kp[(size_t)s0 * 32 + lane];
        float4 kb = kp[(size_t)s1 * 32 + lane];
        float4 va = vp[(size_t)s0 * 32 + lane];
        float4 vb = vp[(size_t)s1 * 32 + lane];

        float pa = q4.x * ka.x + q4.y * ka.y + q4.z * ka.z + q4.w * ka.w;
        float pb = q4.x * kb.x + q4.y * kb.y + q4.z * kb.z + q4.w * kb.w;
        pa += __shfl_xor_sync(0xffffffffu, pa, 1);
        pb += __shfl_xor_sync(0xffffffffu, pb, 1);
        pa += __shfl_xor_sync(0xffffffffu, pa, 2);
        pb += __shfl_xor_sync(0xffffffffu, pb, 2);
        pa += __shfl_xor_sync(0xffffffffu, pa, 4);
        pb += __shfl_xor_sync(0xffffffffu, pb, 4);

        float ba = (t0 == 0) ? b0 : ((t0 == 1) ? b1 : b2);
        float bb = (t1 == 0) ? b0 : ((t1 == 1) ? b1 : b2);
        float ea = __expf(pa * INV_SQRT_HD + ba);
        float eb = __expf(pb * INV_SQRT_HD + bb);
        ssum += ea + eb;
        acc.x += ea * va.x + eb * vb.x;
        acc.y += ea * va.y + eb * vb.y;
        acc.z += ea * va.z + eb * vb.z;
        acc.w += ea * va.w + eb * vb.w;
    }
    if (j < end) {
        int w0 = g_packed[j];
        int s0 = w0 & 0xFFFFF, t0 = w0 >> 20;
        float4 ka = kp[(size_t)s0 * 32 + lane];
        float4 va = vp[(size_t)s0 * 32 + lane];
        float pa = q4.x * ka.x + q4.y * ka.y + q4.z * ka.z + q4.w * ka.w;
        pa += __shfl_xor_sync(0xffffffffu, pa, 1);
        pa += __shfl_xor_sync(0xffffffffu, pa, 2);
        pa += __shfl_xor_sync(0xffffffffu, pa, 4);
        float ba = (t0 == 0) ? b0 : ((t0 == 1) ? b1 : b2);
        float ea = __expf(pa * INV_SQRT_HD + ba);
        ssum += ea;
        acc.x += ea * va.x;
        acc.y += ea * va.y;
        acc.z += ea * va.z;
        acc.w += ea * va.w;
    }

    float inv = 1.f / (ssum + 1e-16f);
    float4 o;
    o.x = acc.x * inv; o.y = acc.y * inv; o.z = acc.z * inv; o.w = acc.w * inv;
    ((float4*)g_att)[(size_t)node * 32 + lane] = o;
}

// ---------------------------------------------------------------- K6: out gemm + LN
__global__ __launch_bounds__(256) void out_ln_kernel(
    const float* __restrict__ x,
    const float* __restrict__ Wo, const float* __restrict__ bo,
    const float* __restrict__ gamma, const float* __restrict__ beta,
    float* __restrict__ out, int n)
{
    __shared__ __align__(16) float sX[64][128];
    __shared__ __align__(16) float sW[32][128];

    int tid  = threadIdx.x;
    int row0 = blockIdx.x * 64;

    for (int i = tid; i < 64 * 32; i += 256) {
        int r = i >> 5, c = i & 31;
        float4 val = make_float4(0.f, 0.f, 0.f, 0.f);
        if (row0 + r < n)
            val = ((const float4*)g_att)[(size_t)(row0 + r) * 32 + c];
        *((float4*)&sX[r][0] + c) = val;
    }

    int warp = tid >> 5, lane = tid & 31;
    int r0 = warp * 8;

    float acc[8][4];
#pragma unroll
    for (int i = 0; i < 8; i++) { acc[i][0] = acc[i][1] = acc[i][2] = acc[i][3] = 0.f; }

    for (int kc = 0; kc < 128; kc += 32) {
        __syncthreads();
        for (int i = tid; i < 32 * 32; i += 256) {
            int r = i >> 5, c = i & 31;
            *((float4*)&sW[r][0] + c) = ((const float4*)Wo)[(size_t)(kc + r) * 32 + c];
        }
        __syncthreads();
#pragma unroll
        for (int kk = 0; kk < 32; kk++) {
            float4 bv4 = *((const float4*)&sW[kk][0] + lane);
#pragma unroll
            for (int i2 = 0; i2 < 8; i2++) {
                float a = sX[r0 + i2][kc + kk];
                acc[i2][0] += a * bv4.x;
                acc[i2][1] += a * bv4.y;
                acc[i2][2] += a * bv4.z;
                acc[i2][3] += a * bv4.w;
            }
        }
    }

    float4 b4 = *((const float4*)bo + lane);
    float4 g4 = *((const float4*)gamma + lane);
    float4 t4 = *((const float4*)beta + lane);

#pragma unroll
    for (int i2 = 0; i2 < 8; i2++) {
        int r = row0 + r0 + i2;
        if (r >= n) continue;
        float4 xr = ((const float4*)x)[(size_t)r * 32 + lane];
        float y0 = acc[i2][0] + b4.x + xr.x;
        float y1 = acc[i2][1] + b4.y + xr.y;
        float y2 = acc[i2][2] + b4.z + xr.z;
        float y3 = acc[i2][3] + b4.w + xr.w;

        float sum = y0 + y1 + y2 + y3;
        float sq  = y0 * y0 + y1 * y1 + y2 * y2 + y3 * y3;
#pragma unroll
        for (int m = 16; m; m >>= 1) {
            sum += __shfl_xor_sync(0xffffffffu, sum, m);
            sq  += __shfl_xor_sync(0xffffffffu, sq, m);
        }
        float mu   = sum * (1.f / 128.f);
        float var  = sq * (1.f / 128.f) - mu * mu;
        float rstd = rsqrtf(var + 1e-5f);

        float4 o;
        o.x = (y0 - mu) * rstd * g4.x + t4.x;
        o.y = (y1 - mu) * rstd * g4.y + t4.y;
        o.z = (y2 - mu) * rstd * g4.z + t4.z;
        o.w = (y3 - mu) * rstd * g4.w + t4.w;
        ((float4*)out)[(size_t)r * 32 + lane] = o;
    }
}

// ---------------------------------------------------------------- launch
extern "C" void kernel_launch(void* const* d_in, const int* in_sizes, int n_in,
                              void* d_out, int out_size)
{
    const float* x     = (const float*)d_in[0];
    const int*   stype = (const int*)d_in[1];
    const int*   eidx  = (const int*)d_in[2];
    const float* Wq    = (const float*)d_in[3];
    const float* bq    = (const float*)d_in[4];
    const float* Wk    = (const float*)d_in[5];
    const float* bk    = (const float*)d_in[6];
    const float* Wv    = (const float*)d_in[7];
    const float* bv    = (const float*)d_in[8];
    const float* sbias = (const float*)d_in[9];
    const float* Wo    = (const float*)d_in[10];
    const float* bo    = (const float*)d_in[11];
    const float* gam   = (const float*)d_in[12];
    const float* bet   = (const float*)d_in[13];

    int n = in_sizes[0] / 128;
    int e = in_sizes[2] / 2;
    const int* src = eidx;
    const int* dst = eidx + e;

    int nb = (n + SCAN_B - 1) / SCAN_B;

    zero_cnt_kernel<<<(n + 255) / 256, 256>>>(n);
    qkv_gemm_kernel<<<dim3((n + 63) / 64, 3), 256>>>(x, Wq, bq, Wk, bk, Wv, bv, n);
    hist_kernel<<<(e + 255) / 256, 256>>>(dst, e);
    scan1_kernel<<<nb, SCAN_B>>>(n);
    scan2_kernel<<<1, 64>>>(nb, n);
    scan3_kernel<<<nb, SCAN_B>>>(n);
    scatter_kernel<<<(e + 255) / 256, 256>>>(src, dst, stype, e);
    gather_kernel<<<((size_t)n * 32 + 255) / 256, 256>>>(sbias, n);
    out_ln_kernel<<<(n + 63) / 64, 256>>>(x, Wo, bo, gam, bet, (float*)d_out, n);
}

// round 4
// speedup vs baseline: 1.7244x; 1.4191x over previous
#include <cuda_runtime.h>

// ---------------------------------------------------------------------------
// StructureAwareAttention on GB300 — Round 4: tf32 tensor-core GEMMs
//   N=50000 nodes, C=128, E=800000 edges, HEADS=4, HEAD_DIM=32
// ---------------------------------------------------------------------------

#define NMAX 50000
#define EMAX 800000
#define SCAN_B 1024

__device__ float g_q[(size_t)NMAX * 128];
__device__ float g_k[(size_t)NMAX * 128];
__device__ float g_v[(size_t)NMAX * 128];
__device__ float g_att[(size_t)NMAX * 128];
__device__ int   g_cnt[NMAX];
__device__ int   g_off[NMAX + 1];
__device__ int   g_cur[NMAX];
__device__ int   g_packed[EMAX];
__device__ int   g_bsum[64];
__device__ int   g_boff[64];

// ---------------------------------------------------------------- helpers
__device__ __forceinline__ float tf32r(float f) {
    unsigned u;
    asm("cvt.rna.tf32.f32 %0, %1;" : "=r"(u) : "f"(f));
    return __uint_as_float(u);
}

__device__ __forceinline__ void mma_tf32(float* d,
    unsigned a0, unsigned a1, unsigned a2, unsigned a3,
    unsigned b0, unsigned b1)
{
    asm volatile(
        "mma.sync.aligned.m16n8k8.row.col.f32.tf32.tf32.f32 "
        "{%0,%1,%2,%3}, {%4,%5,%6,%7}, {%8,%9}, {%0,%1,%2,%3};"
        : "+f"(d[0]), "+f"(d[1]), "+f"(d[2]), "+f"(d[3])
        : "r"(a0), "r"(a1), "r"(a2), "r"(a3), "r"(b0), "r"(b1));
}

// SMEM strides chosen for conflict-free fragment LDS:
//   XS=68:  A-frag bank = (lane>>2)*4 + (lane&3)  -> bijection mod 32
//   WS=136: B-frag bank = (lane&3)*8 + (lane>>2)  -> bijection mod 32
#define XS 68
#define WS 136

// ---------------------------------------------------------------- K0: zero
__global__ void zero_cnt_kernel(int n) {
    int i = blockIdx.x * blockDim.x + threadIdx.x;
    if (i < n) g_cnt[i] = 0;
}

// ---------------------------------------------------------------- K1: QKV GEMM (tf32 MMA)
// Block: 128 thr / 4 warps, tile M=128 x N=128, K=128 (two 64-halves).
// Warp w computes rows [128*bx + 32w, +32) as two m16 tiles.
__global__ __launch_bounds__(128) void qkv_gemm_kernel(
    const float* __restrict__ x,
    const float* __restrict__ Wq, const float* __restrict__ bq,
    const float* __restrict__ Wk, const float* __restrict__ bk,
    const float* __restrict__ Wv, const float* __restrict__ bv,
    int n)
{
    __shared__ __align__(16) float sX[128][XS];
    __shared__ __align__(16) float sW[16][WS];

    const float* W; const float* bias; float* out;
    if (blockIdx.y == 0)      { W = Wq; bias = bq; out = g_q; }
    else if (blockIdx.y == 1) { W = Wk; bias = bk; out = g_k; }
    else                      { W = Wv; bias = bv; out = g_v; }

    int tid  = threadIdx.x;
    int warp = tid >> 5, lane = tid & 31;
    int row0 = blockIdx.x * 128;
    int qr   = lane >> 2;       // 0..7
    int qc   = lane & 3;        // 0..3

    float acc[2][16][4];
#pragma unroll
    for (int m = 0; m < 2; m++)
#pragma unroll
        for (int t = 0; t < 16; t++)
#pragma unroll
            for (int j = 0; j < 4; j++) acc[m][t][j] = 0.f;

    for (int kh = 0; kh < 128; kh += 64) {
        __syncthreads();
        // load X half-tile [128 rows x 64 cols], tf32-rounded
#pragma unroll
        for (int t = 0; t < 16; t++) {
            int i = t * 128 + tid;
            int r = i >> 4, c4 = i & 15;
            float4 v = make_float4(0.f, 0.f, 0.f, 0.f);
            if (row0 + r < n)
                v = ((const float4*)x)[(size_t)(row0 + r) * 32 + (kh >> 2) + c4];
            v.x = tf32r(v.x); v.y = tf32r(v.y); v.z = tf32r(v.z); v.w = tf32r(v.w);
            *((float4*)&sX[r][0] + c4) = v;
        }

        for (int kc = 0; kc < 64; kc += 16) {
            __syncthreads();
#pragma unroll
            for (int t = 0; t < 4; t++) {
                int i = t * 128 + tid;
                int r = i >> 5, c4 = i & 31;
                float4 v = ((const float4*)W)[(size_t)(kh + kc + r) * 32 + c4];
                v.x = tf32r(v.x); v.y = tf32r(v.y); v.z = tf32r(v.z); v.w = tf32r(v.w);
                *((float4*)&sW[r][0] + c4) = v;
            }
            __syncthreads();

#pragma unroll
            for (int ks = 0; ks < 16; ks += 8) {
                int klo = kc + ks;
                unsigned a[2][4];
#pragma unroll
                for (int m = 0; m < 2; m++) {
                    int rb = warp * 32 + m * 16;
                    a[m][0] = __float_as_uint(sX[rb + qr][klo + qc]);
                    a[m][1] = __float_as_uint(sX[rb + qr + 8][klo + qc]);
                    a[m][2] = __float_as_uint(sX[rb + qr][klo + qc + 4]);
                    a[m][3] = __float_as_uint(sX[rb + qr + 8][klo + qc + 4]);
                }
#pragma unroll
                for (int t = 0; t < 16; t++) {
                    unsigned b0 = __float_as_uint(sW[ks + qc][t * 8 + qr]);
                    unsigned b1 = __float_as_uint(sW[ks + 4 + qc][t * 8 + qr]);
                    mma_tf32(acc[0][t], a[0][0], a[0][1], a[0][2], a[0][3], b0, b1);
                    mma_tf32(acc[1][t], a[1][0], a[1][1], a[1][2], a[1][3], b0, b1);
                }
            }
        }
    }

    // epilogue: + bias, store
#pragma unroll
    for (int t = 0; t < 16; t++) {
        int c = t * 8 + qc * 2;
        float2 b2 = *(const float2*)&bias[c];
#pragma unroll
        for (int m = 0; m < 2; m++) {
            int rlo = row0 + warp * 32 + m * 16 + qr;
            if (rlo < n) {
                float2 o; o.x = acc[m][t][0] + b2.x; o.y = acc[m][t][1] + b2.y;
                *(float2*)&out[(size_t)rlo * 128 + c] = o;
            }
            int rhi = rlo + 8;
            if (rhi < n) {
                float2 o; o.x = acc[m][t][2] + b2.x; o.y = acc[m][t][3] + b2.y;
                *(float2*)&out[(size_t)rhi * 128 + c] = o;
            }
        }
    }
}

// ---------------------------------------------------------------- K2: histogram
__global__ void hist_kernel(const int* __restrict__ dst, int e) {
    int i = blockIdx.x * blockDim.x + threadIdx.x;
    if (i < e) atomicAdd(&g_cnt[dst[i]], 1);
}

// ---------------------------------------------------------------- S1: block scan
__global__ __launch_bounds__(SCAN_B) void scan1_kernel(int n) {
    __shared__ int wsum[32];
    int tid  = threadIdx.x;
    int lane = tid & 31, wid = tid >> 5;
    int i = blockIdx.x * SCAN_B + tid;
    int val = (i < n) ? g_cnt[i] : 0;

    int x = val;
#pragma unroll
    for (int d = 1; d < 32; d <<= 1) {
        int t = __shfl_up_sync(0xffffffffu, x, d);
        if (lane >= d) x += t;
    }
    if (lane == 31) wsum[wid] = x;
    __syncthreads();
    if (wid == 0) {
        int w = wsum[lane];
#pragma unroll
        for (int d = 1; d < 32; d <<= 1) {
            int t = __shfl_up_sync(0xffffffffu, w, d);
            if (lane >= d) w += t;
        }
        wsum[lane] = w;
    }
    __syncthreads();
    int base = (wid > 0) ? wsum[wid - 1] : 0;
    int incl = x + base;
    if (i < n) g_off[i] = incl - val;
    if (tid == SCAN_B - 1) g_bsum[blockIdx.x] = incl;
}

// ---------------------------------------------------------------- S2: scan blocks
__global__ void scan2_kernel(int nb, int n) {
    __shared__ int s[64];
    int tid = threadIdx.x;
    int val = (tid < nb) ? g_bsum[tid] : 0;
    s[tid] = val;
    __syncthreads();
#pragma unroll
    for (int d = 1; d < 64; d <<= 1) {
        int t = (tid >= d) ? s[tid - d] : 0;
        __syncthreads();
        s[tid] += t;
        __syncthreads();
    }
    if (tid < nb) g_boff[tid] = s[tid] - val;
    if (tid == 63) g_off[n] = s[63];
}

// ---------------------------------------------------------------- S3: add base
__global__ __launch_bounds__(SCAN_B) void scan3_kernel(int n) {
    int i = blockIdx.x * SCAN_B + threadIdx.x;
    if (i < n) {
        int v = g_off[i] + g_boff[blockIdx.x];
        g_off[i] = v;
        g_cur[i] = v;
    }
}

// ---------------------------------------------------------------- K4: scatter
__global__ void scatter_kernel(const int* __restrict__ src,
                               const int* __restrict__ dst,
                               const int* __restrict__ stype, int e) {
    int i = blockIdx.x * blockDim.x + threadIdx.x;
    if (i < e) {
        int d = dst[i];
        int p = atomicAdd(&g_cur[d], 1);
        int s_ = src[i];
        g_packed[p] = s_ | (stype[s_] << 20);
    }
}

// ---------------------------------------------------------------- K5: gather
__global__ __launch_bounds__(256) void gather_kernel(
    const float* __restrict__ sbias, int n)
{
    int node = (blockIdx.x * blockDim.x + threadIdx.x) >> 5;
    int lane = threadIdx.x & 31;
    if (node >= n) return;

    int head = lane >> 3;
    float b0 = sbias[0 * 4 + head];
    float b1 = sbias[1 * 4 + head];
    float b2 = sbias[2 * 4 + head];

    const float4* kp = (const float4*)g_k;
    const float4* vp = (const float4*)g_v;
    float4 q4 = ((const float4*)g_q)[(size_t)node * 32 + lane];

    float4 acc = make_float4(0.f, 0.f, 0.f, 0.f);
    float ssum = 0.f;
    const float INV_SQRT_HD = 0.17677669529663689f;  // 1/sqrt(32)

    int beg = g_off[node], end = g_off[node + 1];
    int j = beg;
    for (; j + 1 < end; j += 2) {
        int w0 = g_packed[j], w1 = g_packed[j + 1];
        int s0 = w0 & 0xFFFFF, t0 = w0 >> 20;
        int s1 = w1 & 0xFFFFF, t1 = w1 >> 20;
        float4 ka = kp[(size_t)s0 * 32 + lane];
        float4 kb = kp[(size_t)s1 * 32 + lane];
        float4 va = vp[(size_t)s0 * 32 + lane];
        float4 vb = vp[(size_t)s1 * 32 + lane];

        float pa = q4.x * ka.x + q4.y * ka.y + q4.z * ka.z + q4.w * ka.w;
        float pb = q4.x * kb.x + q4.y * kb.y + q4.z * kb.z + q4.w * kb.w;
        pa += __shfl_xor_sync(0xffffffffu, pa, 1);
        pb += __shfl_xor_sync(0xffffffffu, pb, 1);
        pa += __shfl_xor_sync(0xffffffffu, pa, 2);
        pb += __shfl_xor_sync(0xffffffffu, pb, 2);
        pa += __shfl_xor_sync(0xffffffffu, pa, 4);
        pb += __shfl_xor_sync(0xffffffffu, pb, 4);

        float ba = (t0 == 0) ? b0 : ((t0 == 1) ? b1 : b2);
        float bb = (t1 == 0) ? b0 : ((t1 == 1) ? b1 : b2);
        float ea = __expf(pa * INV_SQRT_HD + ba);
        float eb = __expf(pb * INV_SQRT_HD + bb);
        ssum += ea + eb;
        acc.x += ea * va.x + eb * vb.x;
        acc.y += ea * va.y + eb * vb.y;
        acc.z += ea * va.z + eb * vb.z;
        acc.w += ea * va.w + eb * vb.w;
    }
    if (j < end) {
        int w0 = g_packed[j];
        int s0 = w0 & 0xFFFFF, t0 = w0 >> 20;
        float4 ka = kp[(size_t)s0 * 32 + lane];
        float4 va = vp[(size_t)s0 * 32 + lane];
        float pa = q4.x * ka.x + q4.y * ka.y + q4.z * ka.z + q4.w * ka.w;
        pa += __shfl_xor_sync(0xffffffffu, pa, 1);
        pa += __shfl_xor_sync(0xffffffffu, pa, 2);
        pa += __shfl_xor_sync(0xffffffffu, pa, 4);
        float ba = (t0 == 0) ? b0 : ((t0 == 1) ? b1 : b2);
        float ea = __expf(pa * INV_SQRT_HD + ba);
        ssum += ea;
        acc.x += ea * va.x;
        acc.y += ea * va.y;
        acc.z += ea * va.z;
        acc.w += ea * va.w;
    }

    float inv = 1.f / (ssum + 1e-16f);
    float4 o;
    o.x = acc.x * inv; o.y = acc.y * inv; o.z = acc.z * inv; o.w = acc.w * inv;
    ((float4*)g_att)[(size_t)node * 32 + lane] = o;
}

// ---------------------------------------------------------------- K6: out GEMM (tf32 MMA) + LN
__global__ __launch_bounds__(128) void out_ln_kernel(
    const float* __restrict__ x,
    const float* __restrict__ Wo, const float* __restrict__ bo,
    const float* __restrict__ gamma, const float* __restrict__ beta,
    float* __restrict__ out, int n)
{
    __shared__ __align__(16) float sX[128][XS];
    __shared__ __align__(16) float sW[16][WS];

    int tid  = threadIdx.x;
    int warp = tid >> 5, lane = tid & 31;
    int row0 = blockIdx.x * 128;
    int qr   = lane >> 2;
    int qc   = lane & 3;

    float acc[2][16][4];
#pragma unroll
    for (int m = 0; m < 2; m++)
#pragma unroll
        for (int t = 0; t < 16; t++)
#pragma unroll
            for (int j = 0; j < 4; j++) acc[m][t][j] = 0.f;

    for (int kh = 0; kh < 128; kh += 64) {
        __syncthreads();
#pragma unroll
        for (int t = 0; t < 16; t++) {
            int i = t * 128 + tid;
            int r = i >> 4, c4 = i & 15;
            float4 v = make_float4(0.f, 0.f, 0.f, 0.f);
            if (row0 + r < n)
                v = ((const float4*)g_att)[(size_t)(row0 + r) * 32 + (kh >> 2) + c4];
            v.x = tf32r(v.x); v.y = tf32r(v.y); v.z = tf32r(v.z); v.w = tf32r(v.w);
            *((float4*)&sX[r][0] + c4) = v;
        }

        for (int kc = 0; kc < 64; kc += 16) {
            __syncthreads();
#pragma unroll
            for (int t = 0; t < 4; t++) {
                int i = t * 128 + tid;
                int r = i >> 5, c4 = i & 31;
                float4 v = ((const float4*)Wo)[(size_t)(kh + kc + r) * 32 + c4];
                v.x = tf32r(v.x); v.y = tf32r(v.y); v.z = tf32r(v.z); v.w = tf32r(v.w);
                *((float4*)&sW[r][0] + c4) = v;
            }
            __syncthreads();

#pragma unroll
            for (int ks = 0; ks < 16; ks += 8) {
                int klo = kc + ks;
                unsigned a[2][4];
#pragma unroll
                for (int m = 0; m < 2; m++) {
                    int rb = warp * 32 + m * 16;
                    a[m][0] = __float_as_uint(sX[rb + qr][klo + qc]);
                    a[m][1] = __float_as_uint(sX[rb + qr + 8][klo + qc]);
                    a[m][2] = __float_as_uint(sX[rb + qr][klo + qc + 4]);
                    a[m][3] = __float_as_uint(sX[rb + qr + 8][klo + qc + 4]);
                }
#pragma unroll
                for (int t = 0; t < 16; t++) {
                    unsigned b0 = __float_as_uint(sW[ks + qc][t * 8 + qr]);
                    unsigned b1 = __float_as_uint(sW[ks + 4 + qc][t * 8 + qr]);
                    mma_tf32(acc[0][t], a[0][0], a[0][1], a[0][2], a[0][3], b0, b1);
                    mma_tf32(acc[1][t], a[1][0], a[1][1], a[1][2], a[1][3], b0, b1);
                }
            }
        }
    }

    // epilogue: +bias +residual, LayerNorm per row, store.
    // Row slot s: m = s>>1, hi = s&1 -> row = row0 + warp*32 + m*16 + hi*8 + qr
#pragma unroll
    for (int s = 0; s < 4; s++) {
        int m  = s >> 1, hi = s & 1;
        int r  = row0 + warp * 32 + m * 16 + hi * 8 + qr;
        if (r >= n) continue;

        float sum = 0.f, sq = 0.f;
#pragma unroll
        for (int t = 0; t < 16; t++) {
            int c = t * 8 + qc * 2;
            float2 b2 = *(const float2*)&bo[c];
            float2 xr = *(const float2*)&x[(size_t)r * 128 + c];
            float y0 = acc[m][t][hi * 2]     + b2.x + xr.x;
            float y1 = acc[m][t][hi * 2 + 1] + b2.y + xr.y;
            acc[m][t][hi * 2]     = y0;
            acc[m][t][hi * 2 + 1] = y1;
            sum += y0 + y1;
            sq  += y0 * y0 + y1 * y1;
        }
        // reduce across the 4 lanes of this quad (same row)
        sum += __shfl_xor_sync(0xffffffffu, sum, 1);
        sq  += __shfl_xor_sync(0xffffffffu, sq, 1);
        sum += __shfl_xor_sync(0xffffffffu, sum, 2);
        sq  += __shfl_xor_sync(0xffffffffu, sq, 2);

        float mu   = sum * (1.f / 128.f);
        float var  = sq * (1.f / 128.f) - mu * mu;
        float rstd = rsqrtf(var + 1e-5f);

#pragma unroll
        for (int t = 0; t < 16; t++) {
            int c = t * 8 + qc * 2;
            float2 g2 = *(const float2*)&gamma[c];
            float2 t2 = *(const float2*)&beta[c];
            float2 o;
            o.x = (acc[m][t][hi * 2]     - mu) * rstd * g2.x + t2.x;
            o.y = (acc[m][t][hi * 2 + 1] - mu) * rstd * g2.y + t2.y;
            *(float2*)&out[(size_t)r * 128 + c] = o;
        }
    }
}

// ---------------------------------------------------------------- launch
extern "C" void kernel_launch(void* const* d_in, const int* in_sizes, int n_in,
                              void* d_out, int out_size)
{
    const float* x     = (const float*)d_in[0];
    const int*   stype = (const int*)d_in[1];
    const int*   eidx  = (const int*)d_in[2];
    const float* Wq    = (const float*)d_in[3];
    const float* bq    = (const float*)d_in[4];
    const float* Wk    = (const float*)d_in[5];
    const float* bk    = (const float*)d_in[6];
    const float* Wv    = (const float*)d_in[7];
    const float* bv    = (const float*)d_in[8];
    const float* sbias = (const float*)d_in[9];
    const float* Wo    = (const float*)d_in[10];
    const float* bo    = (const float*)d_in[11];
    const float* gam   = (const float*)d_in[12];
    const float* bet   = (const float*)d_in[13];

    int n = in_sizes[0] / 128;
    int e = in_sizes[2] / 2;
    const int* src = eidx;
    const int* dst = eidx + e;

    int nb = (n + SCAN_B - 1) / SCAN_B;
    int gb = (n + 127) / 128;

    zero_cnt_kernel<<<(n + 255) / 256, 256>>>(n);
    qkv_gemm_kernel<<<dim3(gb, 3), 128>>>(x, Wq, bq, Wk, bk, Wv, bv, n);
    hist_kernel<<<(e + 255) / 256, 256>>>(dst, e);
    scan1_kernel<<<nb, SCAN_B>>>(n);
    scan2_kernel<<<1, 64>>>(nb, n);
    scan3_kernel<<<nb, SCAN_B>>>(n);
    scatter_kernel<<<(e + 255) / 256, 256>>>(src, dst, stype, e);
    gather_kernel<<<((size_t)n * 32 + 255) / 256, 256>>>(sbias, n);
    out_ln_kernel<<<gb, 128>>>(x, Wo, bo, gam, bet, (float*)d_out, n);
}